// round 5
// baseline (speedup 1.0000x reference)
#include <cuda_runtime.h>
#include <cub/cub.cuh>

#define NPTS 4096
#define FEAT 128
#define NEDGE (NPTS - 1)
#define NE 8386560                       // NPTS*(NPTS-1)/2
#define SEGPAD 8388608                   // 1<<23
#define PADCNT (SEGPAD - NE)
#define TOTKEYS 16777216
#define SENTK 0xFFFFFFFFFFFFFFFFULL
#define ECAP 4194304
#define CROUNDS 12
#define DROUNDS 2
#define HBINS 2048
#define HOFF 16128                       // (float bits >> 16) offset

// ---------------- static device scratch ----------------
__device__ float g_D[2][(size_t)NPTS * NPTS];
__device__ float g_sq[2][NPTS];
__device__ int g_capBits[2];
__device__ unsigned g_tau[2];
__device__ unsigned g_ncand[2];
__device__ int g_hist[2][HBINS];
__device__ unsigned g_edges[2 * NEDGE];
__device__ unsigned long long g_best[2][NPTS];
__device__ int g_comp[2][NPTS];
__device__ int g_ncomp[2];
__device__ int g_necnt[2];
__device__ unsigned long long g_elist[2][ECAP];     // (dbits<<24)|(a<<12)|b
__device__ __align__(256) unsigned g_keys[TOTKEYS];
__device__ __align__(256) unsigned g_keysAlt[TOTKEYS];
__device__ __align__(256) unsigned char g_temp[1u << 25];
__device__ float g_part[1024];

// ---------------- init ----------------
__global__ void init_kernel() {
    int t = blockIdx.x * blockDim.x + threadIdx.x;
    if (t < PADCNT) {
        g_keys[NE + t] = 0x7F7FFFFFu;
        g_keys[SEGPAD + NE + t] = 0xFFFFFFFFu;
    }
    if (t < HBINS) { g_hist[0][t] = 0; g_hist[1][t] = 0; }
    if (t < NPTS) {
        g_comp[0][t] = t; g_comp[1][t] = t;
        g_best[0][t] = SENTK; g_best[1][t] = SENTK;
    }
    if (t == 0) {
        g_capBits[0] = 0; g_capBits[1] = 0;
        g_ncomp[0] = NPTS; g_ncomp[1] = NPTS;
        g_necnt[0] = 0; g_necnt[1] = 0;
        g_ncand[0] = 0; g_ncand[1] = 0;
    }
}

// ---------------- squared norms ----------------
__global__ void sqnorm_kernel(const float* __restrict__ X1, const float* __restrict__ X2) {
    int g = blockIdx.y;
    const float* __restrict__ X = g ? X2 : X1;
    int row = (blockIdx.x * blockDim.x + threadIdx.x) >> 5;
    int lane = threadIdx.x & 31;
    if (row >= NPTS) return;
    float s = 0.f;
#pragma unroll
    for (int c = lane; c < FEAT; c += 32) { float v = X[row * FEAT + c]; s += v * v; }
#pragma unroll
    for (int o = 16; o; o >>= 1) s += __shfl_down_sync(0xffffffffu, s, o);
    if (lane == 0) g_sq[g][row] = s;
}

// ---------------- distance matrix: 64x64 tiles, 4x4 micro (known-good r3) ----------------
__global__ void dist_kernel(const float* __restrict__ X1, const float* __restrict__ X2) {
    int ti = blockIdx.y, tj = blockIdx.x;
    if (tj < ti) return;
    int g = blockIdx.z;
    const float* __restrict__ X = g ? X2 : X1;

    __shared__ __align__(16) float As[16][68];
    __shared__ __align__(16) float Bs[16][68];
    __shared__ float smax[256];

    int tx = threadIdx.x, ty = threadIdx.y;
    int tid = ty * 16 + tx;
    int i0 = ti * 64, j0 = tj * 64;

    float acc[4][4];
#pragma unroll
    for (int r = 0; r < 4; r++)
#pragma unroll
        for (int c = 0; c < 4; c++) acc[r][c] = 0.f;

    for (int k0 = 0; k0 < FEAT; k0 += 16) {
#pragma unroll
        for (int l = 0; l < 4; l++) {
            int lin = tid + l * 256;
            int m = lin >> 4, kk = lin & 15;
            As[kk][m] = X[(i0 + m) * FEAT + k0 + kk];
            Bs[kk][m] = X[(j0 + m) * FEAT + k0 + kk];
        }
        __syncthreads();
#pragma unroll
        for (int k = 0; k < 16; k++) {
            float4 a4 = *(const float4*)&As[k][ty * 4];
            float4 b4 = *(const float4*)&Bs[k][tx * 4];
            float av[4] = {a4.x, a4.y, a4.z, a4.w};
            float bv[4] = {b4.x, b4.y, b4.z, b4.w};
#pragma unroll
            for (int r = 0; r < 4; r++)
#pragma unroll
                for (int c = 0; c < 4; c++) acc[r][c] += av[r] * bv[c];
        }
        __syncthreads();
    }

    float sqi[4], sqj[4];
#pragma unroll
    for (int r = 0; r < 4; r++) {
        sqi[r] = g_sq[g][i0 + ty * 4 + r];
        sqj[r] = g_sq[g][j0 + tx * 4 + r];
    }
    float* Dg = g_D[g];
    float dval[4][4];
    float lmax = 0.f;
#pragma unroll
    for (int r = 0; r < 4; r++) {
#pragma unroll
        for (int c = 0; c < 4; c++) {
            float d2 = sqi[r] + sqj[c] - 2.f * acc[r][c];
            d2 = fmaxf(d2, 0.f);
            float d = (d2 > 1e-12f) ? sqrtf(d2) : 0.f;
            dval[r][c] = d;
            lmax = fmaxf(lmax, d);
        }
        float4 v = make_float4(dval[r][0], dval[r][1], dval[r][2], dval[r][3]);
        *(float4*)&Dg[(size_t)(i0 + ty * 4 + r) * NPTS + j0 + tx * 4] = v;
    }
    if (ti != tj) {
#pragma unroll
        for (int c = 0; c < 4; c++) {
            float4 v = make_float4(dval[0][c], dval[1][c], dval[2][c], dval[3][c]);
            *(float4*)&Dg[(size_t)(j0 + tx * 4 + c) * NPTS + i0 + ty * 4] = v;
        }
    }
    smax[tid] = lmax;
    __syncthreads();
    for (int o = 128; o; o >>= 1) {
        if (tid < o) smax[tid] = fmaxf(smax[tid], smax[tid + o]);
        __syncthreads();
    }
    if (tid == 0) atomicMax(&g_capBits[g], __float_as_int(smax[0]));
}

// ---------------- histogram of sampled distance bits (parallel) ----------------
__global__ void hist_kernel() {
    int g = blockIdx.y;
    __shared__ int h[HBINS];
    int t = threadIdx.x;
    for (int i = t; i < HBINS; i += 256) h[i] = 0;
    __syncthreads();
    const float* __restrict__ D = g_D[g];
#pragma unroll
    for (int s = 0; s < 4; s++) {
        unsigned gid = blockIdx.x * 1024 + t * 4 + s;
        unsigned idx = (gid * 2654435761u) & (unsigned)(NPTS * NPTS - 1);
        int db = __float_as_int(D[idx]);
        if (db > 0) {
            int b = min(max((db >> 16) - HOFF, 0), HBINS - 1);
            atomicAdd(&h[b], 1);
        }
    }
    __syncthreads();
    for (int i = t; i < HBINS; i += 256)
        if (h[i]) atomicAdd(&g_hist[g][i], h[i]);
}

// ---------------- tau: 1/16 quantile from histogram (block scan) ----------------
__global__ void __launch_bounds__(1024) tau_kernel() {
    int g = blockIdx.x;
    __shared__ int h[HBINS], h2[HBINS];
    __shared__ int sbin;
    int t = threadIdx.x;
    for (int i = t; i < HBINS; i += 1024) h[i] = g_hist[g][i];
    if (t == 0) sbin = HBINS - 1;
    __syncthreads();
    int* cur = h;
    int* nxt = h2;
    for (int off = 1; off < HBINS; off <<= 1) {
        for (int i = t; i < HBINS; i += 1024)
            nxt[i] = cur[i] + (i >= off ? cur[i - off] : 0);
        __syncthreads();
        int* tmp = cur; cur = nxt; nxt = tmp;
    }
    int target = 65536 / 16;  // 1/16 quantile of ~65536 samples
    for (int i = t; i < HBINS; i += 1024)
        if (cur[i] >= target && (i == 0 || cur[i - 1] < target)) atomicMin(&sbin, i);
    __syncthreads();
    if (t == 0) g_tau[g] = (unsigned)(sbin + 1 + HOFF) << 16;
}

// ---------------- persistence keys + fused candidate-edge compaction ----------------
__global__ void pfill_kernel() {
    int g = blockIdx.y;
    size_t idx = (size_t)blockIdx.x * blockDim.x + threadIdx.x;
    int i = (int)(idx >> 12);
    int j = (int)(idx & (NPTS - 1));
    bool up = (j > i);
    unsigned db = 0;
    if (up) {
        db = __float_as_uint(g_D[g][idx]);
        float cap = __int_as_float(g_capBits[g]);
        float per = cap - __uint_as_float(db);
        unsigned k = (unsigned)(((long long)i * (2 * NPTS - i - 1)) >> 1) + (unsigned)(j - i - 1);
        g_keys[(size_t)g * SEGPAD + k] = __float_as_uint(per) | (((unsigned)g) << 31);
    }
    bool w = up && (db < g_tau[g]);
    unsigned mask = __ballot_sync(0xffffffffu, w);
    if (w) {
        int lane = threadIdx.x & 31;
        int leader = __ffs(mask) - 1;
        int rank = __popc(mask & ((1u << lane) - 1));
        unsigned base = 0;
        if (lane == leader) base = atomicAdd(&g_ncand[g], (unsigned)__popc(mask));
        base = __shfl_sync(mask, base, leader);
        unsigned slot = base + rank;
        if (slot < ECAP)
            g_elist[g][slot] = ((unsigned long long)db << 24) | (unsigned)((i << 12) | j);
    }
}

// ---------------- fused Boruvka round: scan + merge, one block per graph ----------------
__global__ void __launch_bounds__(1024) round_kernel() {
    int g = blockIdx.x;
    if (g_ncomp[g] <= 1) return;
    unsigned E = g_ncand[g];
    if (E > ECAP) return;  // incomplete list would break cut property; dense handles

    __shared__ unsigned long long sbest[NPTS];                 // 32 KB
    __shared__ union { unsigned short comp[NPTS]; unsigned short par[NPTS]; } u;  // 8 KB
    __shared__ int scnt;
    int t = threadIdx.x;
    for (int i = t; i < NPTS; i += 1024) {
        u.comp[i] = (unsigned short)g_comp[g][i];
        sbest[i] = SENTK;
    }
    if (t == 0) scnt = 0;
    __syncthreads();

    // phase 1: min outgoing edge per component (shared atomics)
    const unsigned long long* __restrict__ el = g_elist[g];
    for (unsigned e = t; e < E; e += 1024) {
        unsigned long long k = el[e];
        unsigned eid = (unsigned)(k & 0xFFFFFFu);
        int cu = u.comp[eid >> 12], cv = u.comp[eid & 4095];
        if (cu != cv) {
            if (k < sbest[cu]) atomicMin(&sbest[cu], k);
            if (k < sbest[cv]) atomicMin(&sbest[cv], k);
        }
    }
    __syncthreads();

    // phase 2: link (reads g_comp from global; u switches to par)
    __syncthreads();
    for (int v = t; v < NPTS; v += 1024) u.par[v] = (unsigned short)v;
    __syncthreads();
    for (int v = t; v < NPTS; v += 1024) {
        unsigned long long bk = sbest[v];
        if (bk != SENTK) {
            unsigned eid = (unsigned)(bk & 0xFFFFFFu);
            int a = (int)(eid >> 12), b = (int)(eid & 4095);
            int ca = g_comp[g][a], cb = g_comp[g][b];
            int other = (ca == v) ? cb : ca;
            bool add = !(sbest[other] == bk && other < v);
            if (add) {
                int slot = atomicAdd(&g_necnt[g], 1);
                if (slot < NEDGE) g_edges[g * NEDGE + slot] = eid;
            }
            u.par[v] = (unsigned short)other;
        }
    }
    __syncthreads();
    // break 2-cycles
    for (int v = t; v < NPTS; v += 1024) {
        int p = u.par[v];
        if (p != v && u.par[p] == v && v < p) u.par[v] = (unsigned short)v;
    }
    __syncthreads();
    // pointer jumping
    for (int it = 0; it < 13; it++) {
        for (int v = t; v < NPTS; v += 1024) u.par[v] = u.par[u.par[v]];
        __syncthreads();
    }
    // relabel + count
    for (int i = t; i < NPTS; i += 1024)
        g_comp[g][i] = u.par[g_comp[g][i]];
    __syncthreads();
    int local = 0;
    for (int i = t; i < NPTS; i += 1024)
        if (g_comp[g][i] == i) local++;
    atomicAdd(&scnt, local);
    __syncthreads();
    if (t == 0) g_ncomp[g] = scnt;
}

// ---------------- dense Boruvka safety (unchanged, no-op when converged) ----------------
__global__ void __launch_bounds__(256) bmin_kernel() {
    int g = blockIdx.y;
    if (g_ncomp[g] <= 1) return;
    __shared__ int scomp[NPTS];
    int t = threadIdx.x;
    for (int i = t; i < NPTS; i += 256) scomp[i] = g_comp[g][i];
    __syncthreads();
    int warp = t >> 5, lane = t & 31;
    int r = blockIdx.x * 8 + warp;
    int myc = scomp[r];
    const float* __restrict__ row = g_D[g] + (size_t)r * NPTS;
    unsigned long long best = SENTK;
    for (int j0 = lane * 4; j0 < NPTS; j0 += 128) {
        float4 v = *(const float4*)(row + j0);
        float dv[4] = {v.x, v.y, v.z, v.w};
#pragma unroll
        for (int uu = 0; uu < 4; uu++) {
            int j = j0 + uu;
            if (scomp[j] != myc) {
                int a = min(r, j), b = max(r, j);
                unsigned long long k =
                    ((unsigned long long)__float_as_uint(dv[uu]) << 24) |
                    (unsigned)((a << 12) | b);
                if (k < best) best = k;
            }
        }
    }
#pragma unroll
    for (int o = 16; o; o >>= 1) {
        unsigned long long ov = __shfl_down_sync(0xffffffffu, best, o);
        if (ov < best) best = ov;
    }
    if (lane == 0 && best != SENTK) atomicMin(&g_best[g][myc], best);
}

__global__ void __launch_bounds__(1024) bmerge_kernel() {
    int g = blockIdx.x;
    if (g_ncomp[g] <= 1) return;
    __shared__ int par[NPTS];
    __shared__ int scnt;
    int t = threadIdx.x;
    for (int i = t; i < NPTS; i += 1024) par[i] = i;
    if (t == 0) scnt = 0;
    __syncthreads();
    for (int v = t; v < NPTS; v += 1024) {
        unsigned long long bk = g_best[g][v];
        if (bk != SENTK) {
            unsigned eid = (unsigned)(bk & 0xFFFFFFu);
            int a = (int)(eid >> 12), b = (int)(eid & 4095);
            int ca = g_comp[g][a], cb = g_comp[g][b];
            int other = (ca == v) ? cb : ca;
            bool add = !(g_best[g][other] == bk && other < v);
            if (add) {
                int slot = atomicAdd(&g_necnt[g], 1);
                if (slot < NEDGE) g_edges[g * NEDGE + slot] = eid;
            }
            par[v] = other;
        }
    }
    __syncthreads();
    for (int v = t; v < NPTS; v += 1024) {
        int p = par[v];
        if (p != v && par[p] == v && v < p) par[v] = v;
    }
    __syncthreads();
    for (int it = 0; it < 13; it++) {
        for (int v = t; v < NPTS; v += 1024) par[v] = par[par[v]];
        __syncthreads();
    }
    for (int i = t; i < NPTS; i += 1024) {
        g_comp[g][i] = par[g_comp[g][i]];
        g_best[g][i] = SENTK;
    }
    __syncthreads();
    int local = 0;
    for (int i = t; i < NPTS; i += 1024)
        if (g_comp[g][i] == i) local++;
    atomicAdd(&scnt, local);
    __syncthreads();
    if (t == 0) g_ncomp[g] = scnt;
}

// ---------------- zero-out tree edges ----------------
__global__ void fixup_kernel() {
    int e = blockIdx.x * blockDim.x + threadIdx.x;
    if (e >= 2 * NEDGE) return;
    int g = e / NEDGE;
    int i = e % NEDGE;
    unsigned pk = g_edges[g * NEDGE + i];
    int u = (int)(pk >> 12), v = (int)(pk & 4095);
    int a = u < v ? u : v;
    int b = u < v ? v : u;
    unsigned k = (unsigned)(((long long)a * (2 * NPTS - a - 1)) >> 1) + (unsigned)(b - a - 1);
    g_keys[(size_t)g * SEGPAD + k] = ((unsigned)g) << 31;
}

// ---------------- Wasserstein sum ----------------
__global__ void wsum1_kernel(const unsigned* __restrict__ keys) {
    __shared__ float sh[256];
    float s = 0.f;
    for (size_t k = (size_t)blockIdx.x * blockDim.x + threadIdx.x; k < NE;
         k += (size_t)gridDim.x * blockDim.x) {
        float a = __uint_as_float(keys[k]);
        float b = __uint_as_float(keys[SEGPAD + k] & 0x7FFFFFFFu);
        s += fabsf(a - b);
    }
    sh[threadIdx.x] = s;
    __syncthreads();
    for (int o = 128; o; o >>= 1) {
        if (threadIdx.x < o) sh[threadIdx.x] += sh[threadIdx.x + o];
        __syncthreads();
    }
    if (threadIdx.x == 0) g_part[blockIdx.x] = sh[0];
}

__global__ void wsum2_kernel(float* __restrict__ out) {
    __shared__ double sh[1024];
    sh[threadIdx.x] = (double)g_part[threadIdx.x];
    __syncthreads();
    for (int o = 512; o; o >>= 1) {
        if (threadIdx.x < o) sh[threadIdx.x] += sh[threadIdx.x + o];
        __syncthreads();
    }
    if (threadIdx.x == 0) out[0] = (float)sh[0];
}

// ---------------- launch ----------------
extern "C" void kernel_launch(void* const* d_in, const int* in_sizes, int n_in,
                              void* d_out, int out_size) {
    const float* X1 = (const float*)d_in[0];
    const float* X2 = (const float*)d_in[2];
    float* out = (float*)d_out;

    init_kernel<<<16, 256>>>();
    sqnorm_kernel<<<dim3(NPTS / 8, 2), 256>>>(X1, X2);
    dist_kernel<<<dim3(64, 64, 2), dim3(16, 16)>>>(X1, X2);
    hist_kernel<<<dim3(64, 2), 256>>>();
    tau_kernel<<<2, 1024>>>();
    pfill_kernel<<<dim3((NPTS * NPTS) / 256, 2), 256>>>();

    for (int r = 0; r < CROUNDS; r++) round_kernel<<<2, 1024>>>();
    for (int r = 0; r < DROUNDS; r++) {
        bmin_kernel<<<dim3(NPTS / 8, 2), 256>>>();
        bmerge_kernel<<<2, 1024>>>();
    }

    fixup_kernel<<<(2 * NEDGE + 255) / 256, 256>>>();

    unsigned *keys, *alt;
    void* tempp;
    cudaGetSymbolAddress((void**)&keys, g_keys);
    cudaGetSymbolAddress((void**)&alt, g_keysAlt);
    cudaGetSymbolAddress(&tempp, g_temp);

    cub::DoubleBuffer<unsigned> db(keys, alt);
    size_t bytes = 0;
    cub::DeviceRadixSort::SortKeys(nullptr, bytes, db, TOTKEYS, 0, 32, (cudaStream_t)0);
    cub::DeviceRadixSort::SortKeys(tempp, bytes, db, TOTKEYS, 0, 32, (cudaStream_t)0);

    const unsigned* sorted = db.Current();
    wsum1_kernel<<<1024, 256>>>(sorted);
    wsum2_kernel<<<1, 1024>>>(out);
}

// round 6
// speedup vs baseline: 3.6971x; 3.6971x over previous
#include <cuda_runtime.h>
#include <cub/cub.cuh>

#define NPTS 4096
#define FEAT 128
#define NEDGE (NPTS - 1)
#define NE 8386560                       // NPTS*(NPTS-1)/2
#define SEGPAD 8388608                   // 1<<23
#define PADCNT (SEGPAD - NE)
#define TOTKEYS 16777216
#define SENTK 0xFFFFFFFFFFFFFFFFULL
#define ECAP 4194304
#define CROUNDS 12
#define DROUNDS 2
#define HBINS 2048

// ---------------- static device scratch ----------------
__device__ float g_D[2][(size_t)NPTS * NPTS];
__device__ float g_sq[2][NPTS];
__device__ int g_capBits[2];
__device__ int g_minB[2], g_maxB[2], g_nsamp[2];
__device__ unsigned g_tau[2];
__device__ unsigned g_ncand[2];
__device__ int g_hist[2][HBINS];
__device__ unsigned g_edges[2 * NEDGE];
__device__ unsigned long long g_best[2][NPTS];
__device__ int g_comp[2][NPTS];
__device__ int g_ncomp[2];
__device__ int g_necnt[2];
__device__ unsigned long long g_elist[2][ECAP];     // (dbits<<24)|(a<<12)|b
__device__ __align__(256) unsigned g_keys[TOTKEYS];
__device__ __align__(256) unsigned g_keysAlt[TOTKEYS];
__device__ __align__(256) unsigned char g_temp[1u << 25];
__device__ float g_part[1024];

// ---------------- init ----------------
__global__ void init_kernel() {
    int t = blockIdx.x * blockDim.x + threadIdx.x;
    if (t < PADCNT) {
        g_keys[NE + t] = 0x7F7FFFFFu;
        g_keys[SEGPAD + NE + t] = 0xFFFFFFFFu;
    }
    if (t < HBINS) { g_hist[0][t] = 0; g_hist[1][t] = 0; }
    if (t < NPTS) {
        g_comp[0][t] = t; g_comp[1][t] = t;
        g_best[0][t] = SENTK; g_best[1][t] = SENTK;
    }
    if (t == 0) {
        g_capBits[0] = 0; g_capBits[1] = 0;
        g_minB[0] = 0x7FFFFFFF; g_minB[1] = 0x7FFFFFFF;
        g_maxB[0] = 0; g_maxB[1] = 0;
        g_nsamp[0] = 0; g_nsamp[1] = 0;
        g_ncomp[0] = NPTS; g_ncomp[1] = NPTS;
        g_necnt[0] = 0; g_necnt[1] = 0;
        g_ncand[0] = 0; g_ncand[1] = 0;
    }
}

// ---------------- squared norms ----------------
__global__ void sqnorm_kernel(const float* __restrict__ X1, const float* __restrict__ X2) {
    int g = blockIdx.y;
    const float* __restrict__ X = g ? X2 : X1;
    int row = (blockIdx.x * blockDim.x + threadIdx.x) >> 5;
    int lane = threadIdx.x & 31;
    if (row >= NPTS) return;
    float s = 0.f;
#pragma unroll
    for (int c = lane; c < FEAT; c += 32) { float v = X[row * FEAT + c]; s += v * v; }
#pragma unroll
    for (int o = 16; o; o >>= 1) s += __shfl_down_sync(0xffffffffu, s, o);
    if (lane == 0) g_sq[g][row] = s;
}

// ---------------- distance matrix: 64x64 tiles, 4x4 micro (known-good) ----------------
__global__ void dist_kernel(const float* __restrict__ X1, const float* __restrict__ X2) {
    int ti = blockIdx.y, tj = blockIdx.x;
    if (tj < ti) return;
    int g = blockIdx.z;
    const float* __restrict__ X = g ? X2 : X1;

    __shared__ __align__(16) float As[16][68];
    __shared__ __align__(16) float Bs[16][68];
    __shared__ float smax[256];

    int tx = threadIdx.x, ty = threadIdx.y;
    int tid = ty * 16 + tx;
    int i0 = ti * 64, j0 = tj * 64;

    float acc[4][4];
#pragma unroll
    for (int r = 0; r < 4; r++)
#pragma unroll
        for (int c = 0; c < 4; c++) acc[r][c] = 0.f;

    for (int k0 = 0; k0 < FEAT; k0 += 16) {
#pragma unroll
        for (int l = 0; l < 4; l++) {
            int lin = tid + l * 256;
            int m = lin >> 4, kk = lin & 15;
            As[kk][m] = X[(i0 + m) * FEAT + k0 + kk];
            Bs[kk][m] = X[(j0 + m) * FEAT + k0 + kk];
        }
        __syncthreads();
#pragma unroll
        for (int k = 0; k < 16; k++) {
            float4 a4 = *(const float4*)&As[k][ty * 4];
            float4 b4 = *(const float4*)&Bs[k][tx * 4];
            float av[4] = {a4.x, a4.y, a4.z, a4.w};
            float bv[4] = {b4.x, b4.y, b4.z, b4.w};
#pragma unroll
            for (int r = 0; r < 4; r++)
#pragma unroll
                for (int c = 0; c < 4; c++) acc[r][c] += av[r] * bv[c];
        }
        __syncthreads();
    }

    float sqi[4], sqj[4];
#pragma unroll
    for (int r = 0; r < 4; r++) {
        sqi[r] = g_sq[g][i0 + ty * 4 + r];
        sqj[r] = g_sq[g][j0 + tx * 4 + r];
    }
    float* Dg = g_D[g];
    float dval[4][4];
    float lmax = 0.f;
#pragma unroll
    for (int r = 0; r < 4; r++) {
#pragma unroll
        for (int c = 0; c < 4; c++) {
            float d2 = sqi[r] + sqj[c] - 2.f * acc[r][c];
            d2 = fmaxf(d2, 0.f);
            float d = (d2 > 1e-12f) ? sqrtf(d2) : 0.f;
            dval[r][c] = d;
            lmax = fmaxf(lmax, d);
        }
        float4 v = make_float4(dval[r][0], dval[r][1], dval[r][2], dval[r][3]);
        *(float4*)&Dg[(size_t)(i0 + ty * 4 + r) * NPTS + j0 + tx * 4] = v;
    }
    if (ti != tj) {
#pragma unroll
        for (int c = 0; c < 4; c++) {
            float4 v = make_float4(dval[0][c], dval[1][c], dval[2][c], dval[3][c]);
            *(float4*)&Dg[(size_t)(j0 + tx * 4 + c) * NPTS + i0 + ty * 4] = v;
        }
    }
    smax[tid] = lmax;
    __syncthreads();
    for (int o = 128; o; o >>= 1) {
        if (tid < o) smax[tid] = fmaxf(smax[tid], smax[tid + o]);
        __syncthreads();
    }
    if (tid == 0) atomicMax(&g_capBits[g], __float_as_int(smax[0]));
}

// ---------------- sampled min/max of distance bits ----------------
__global__ void minmax_kernel() {
    int g = blockIdx.y;
    int t = blockIdx.x * 256 + threadIdx.x;     // grid (32,2): 8192 threads
    const float* __restrict__ D = g_D[g];
    int lmin = 0x7FFFFFFF, lmax = 0;
#pragma unroll
    for (int s = 0; s < 8; s++) {
        unsigned gid = (unsigned)t * 8 + s;
        unsigned idx = (gid * 2654435761u) & (unsigned)(NPTS * NPTS - 1);
        int db = __float_as_int(D[idx]);
        if (db > 0) { lmin = min(lmin, db); lmax = max(lmax, db); }
    }
#pragma unroll
    for (int o = 16; o; o >>= 1) {
        lmin = min(lmin, __shfl_down_sync(0xffffffffu, lmin, o));
        lmax = max(lmax, __shfl_down_sync(0xffffffffu, lmax, o));
    }
    if ((threadIdx.x & 31) == 0) {
        atomicMin(&g_minB[g], lmin);
        atomicMax(&g_maxB[g], lmax);
    }
}

// ---------------- fine histogram over [min,max] ----------------
__global__ void hist_kernel() {
    int g = blockIdx.y;
    __shared__ int h[HBINS];
    __shared__ int svalid;
    int t = threadIdx.x;
    for (int i = t; i < HBINS; i += 256) h[i] = 0;
    if (t == 0) svalid = 0;
    __syncthreads();
    unsigned minB = (unsigned)g_minB[g];
    unsigned long long range = (unsigned long long)((unsigned)g_maxB[g] - minB) + 1;
    const float* __restrict__ D = g_D[g];
    int lval = 0;
#pragma unroll
    for (int s = 0; s < 4; s++) {
        unsigned gid = blockIdx.x * 1024 + t * 4 + s;
        unsigned idx = (gid * 2654435761u) & (unsigned)(NPTS * NPTS - 1);
        int db = __float_as_int(D[idx]);
        if (db > 0) {
            int b = (int)(((unsigned long long)((unsigned)db - minB) * HBINS) / range);
            atomicAdd(&h[min(b, HBINS - 1)], 1);
            lval++;
        }
    }
    atomicAdd(&svalid, lval);
    __syncthreads();
    for (int i = t; i < HBINS; i += 256)
        if (h[i]) atomicAdd(&g_hist[g][i], h[i]);
    if (t == 0) atomicAdd(&g_nsamp[g], svalid);
}

// ---------------- tau: 1/32 quantile from histogram ----------------
__global__ void __launch_bounds__(1024) tau_kernel() {
    int g = blockIdx.x;
    __shared__ int h[HBINS], h2[HBINS];
    __shared__ int sbin;
    int t = threadIdx.x;
    for (int i = t; i < HBINS; i += 1024) h[i] = g_hist[g][i];
    if (t == 0) sbin = HBINS - 1;
    __syncthreads();
    int* cur = h;
    int* nxt = h2;
    for (int off = 1; off < HBINS; off <<= 1) {
        for (int i = t; i < HBINS; i += 1024)
            nxt[i] = cur[i] + (i >= off ? cur[i - off] : 0);
        __syncthreads();
        int* tmp = cur; cur = nxt; nxt = tmp;
    }
    int target = g_nsamp[g] / 32;   // avg degree ~128
    for (int i = t; i < HBINS; i += 1024)
        if (cur[i] >= target && (i == 0 || cur[i - 1] < target)) atomicMin(&sbin, i);
    __syncthreads();
    if (t == 0) {
        unsigned minB = (unsigned)g_minB[g];
        unsigned long long range = (unsigned long long)((unsigned)g_maxB[g] - minB) + 1;
        g_tau[g] = minB + (unsigned)(((unsigned long long)(sbin + 1) * range) / HBINS);
    }
}

// ---------------- persistence keys + fused candidate-edge compaction ----------------
__global__ void pfill_kernel() {
    int g = blockIdx.y;
    size_t idx = (size_t)blockIdx.x * blockDim.x + threadIdx.x;
    int i = (int)(idx >> 12);
    int j = (int)(idx & (NPTS - 1));
    bool up = (j > i);
    unsigned db = 0;
    if (up) {
        db = __float_as_uint(g_D[g][idx]);
        float cap = __int_as_float(g_capBits[g]);
        float per = cap - __uint_as_float(db);
        unsigned k = (unsigned)(((long long)i * (2 * NPTS - i - 1)) >> 1) + (unsigned)(j - i - 1);
        g_keys[(size_t)g * SEGPAD + k] = __float_as_uint(per) | (((unsigned)g) << 31);
    }
    bool w = up && (db < g_tau[g]);
    unsigned mask = __ballot_sync(0xffffffffu, w);
    if (w) {
        int lane = threadIdx.x & 31;
        int leader = __ffs(mask) - 1;
        int rank = __popc(mask & ((1u << lane) - 1));
        unsigned base = 0;
        if (lane == leader) base = atomicAdd(&g_ncand[g], (unsigned)__popc(mask));
        base = __shfl_sync(mask, base, leader);
        unsigned slot = base + rank;
        if (slot < ECAP)
            g_elist[g][slot] = ((unsigned long long)db << 24) | (unsigned)((i << 12) | j);
    }
}

// ---------------- compact-list scan: multi-block, global atomicMin ----------------
__global__ void __launch_bounds__(256) cmin_kernel() {
    int g = blockIdx.y;
    if (g_ncomp[g] <= 1) return;
    unsigned E = g_ncand[g];
    if (E > ECAP) return;  // incomplete list unsafe; dense rounds handle
    const unsigned long long* __restrict__ el = g_elist[g];
    const int* __restrict__ comp = g_comp[g];
    for (unsigned e = blockIdx.x * 256 + threadIdx.x; e < E; e += gridDim.x * 256) {
        unsigned long long k = el[e];
        unsigned eid = (unsigned)(k & 0xFFFFFFu);
        int cu = __ldg(&comp[eid >> 12]), cv = __ldg(&comp[eid & 4095]);
        if (cu != cv) {
            if (k < g_best[g][cu]) atomicMin(&g_best[g][cu], k);
            if (k < g_best[g][cv]) atomicMin(&g_best[g][cv], k);
        }
    }
}

// ---------------- dense Boruvka safety scan ----------------
__global__ void __launch_bounds__(256) bmin_kernel() {
    int g = blockIdx.y;
    if (g_ncomp[g] <= 1) return;
    __shared__ int scomp[NPTS];
    int t = threadIdx.x;
    for (int i = t; i < NPTS; i += 256) scomp[i] = g_comp[g][i];
    __syncthreads();
    int warp = t >> 5, lane = t & 31;
    int r = blockIdx.x * 8 + warp;
    int myc = scomp[r];
    const float* __restrict__ row = g_D[g] + (size_t)r * NPTS;
    unsigned long long best = SENTK;
    for (int j0 = lane * 4; j0 < NPTS; j0 += 128) {
        float4 v = *(const float4*)(row + j0);
        float dv[4] = {v.x, v.y, v.z, v.w};
#pragma unroll
        for (int uu = 0; uu < 4; uu++) {
            int j = j0 + uu;
            if (scomp[j] != myc) {
                int a = min(r, j), b = max(r, j);
                unsigned long long k =
                    ((unsigned long long)__float_as_uint(dv[uu]) << 24) |
                    (unsigned)((a << 12) | b);
                if (k < best) best = k;
            }
        }
    }
#pragma unroll
    for (int o = 16; o; o >>= 1) {
        unsigned long long ov = __shfl_down_sync(0xffffffffu, best, o);
        if (ov < best) best = ov;
    }
    if (lane == 0 && best != SENTK) atomicMin(&g_best[g][myc], best);
}

// ---------------- merge components (1 block/graph, O(N) work only) ----------------
__global__ void __launch_bounds__(1024) bmerge_kernel() {
    int g = blockIdx.x;
    if (g_ncomp[g] <= 1) return;
    __shared__ int par[NPTS];
    __shared__ int scnt;
    int t = threadIdx.x;
    for (int i = t; i < NPTS; i += 1024) par[i] = i;
    if (t == 0) scnt = 0;
    __syncthreads();
    for (int v = t; v < NPTS; v += 1024) {
        unsigned long long bk = g_best[g][v];
        if (bk != SENTK) {
            unsigned eid = (unsigned)(bk & 0xFFFFFFu);
            int a = (int)(eid >> 12), b = (int)(eid & 4095);
            int ca = g_comp[g][a], cb = g_comp[g][b];
            int other = (ca == v) ? cb : ca;
            bool add = !(g_best[g][other] == bk && other < v);
            if (add) {
                int slot = atomicAdd(&g_necnt[g], 1);
                if (slot < NEDGE) g_edges[g * NEDGE + slot] = eid;
            }
            par[v] = other;
        }
    }
    __syncthreads();
    for (int v = t; v < NPTS; v += 1024) {
        int p = par[v];
        if (p != v && par[p] == v && v < p) par[v] = v;
    }
    __syncthreads();
    for (int it = 0; it < 13; it++) {
        for (int v = t; v < NPTS; v += 1024) par[v] = par[par[v]];
        __syncthreads();
    }
    for (int i = t; i < NPTS; i += 1024) {
        g_comp[g][i] = par[g_comp[g][i]];
        g_best[g][i] = SENTK;
    }
    __syncthreads();
    int local = 0;
    for (int i = t; i < NPTS; i += 1024)
        if (g_comp[g][i] == i) local++;
    atomicAdd(&scnt, local);
    __syncthreads();
    if (t == 0) g_ncomp[g] = scnt;
}

// ---------------- zero-out tree edges ----------------
__global__ void fixup_kernel() {
    int e = blockIdx.x * blockDim.x + threadIdx.x;
    if (e >= 2 * NEDGE) return;
    int g = e / NEDGE;
    int i = e % NEDGE;
    unsigned pk = g_edges[g * NEDGE + i];
    int u = (int)(pk >> 12), v = (int)(pk & 4095);
    int a = u < v ? u : v;
    int b = u < v ? v : u;
    unsigned k = (unsigned)(((long long)a * (2 * NPTS - a - 1)) >> 1) + (unsigned)(b - a - 1);
    g_keys[(size_t)g * SEGPAD + k] = ((unsigned)g) << 31;
}

// ---------------- Wasserstein sum ----------------
__global__ void wsum1_kernel(const unsigned* __restrict__ keys) {
    __shared__ float sh[256];
    float s = 0.f;
    for (size_t k = (size_t)blockIdx.x * blockDim.x + threadIdx.x; k < NE;
         k += (size_t)gridDim.x * blockDim.x) {
        float a = __uint_as_float(keys[k]);
        float b = __uint_as_float(keys[SEGPAD + k] & 0x7FFFFFFFu);
        s += fabsf(a - b);
    }
    sh[threadIdx.x] = s;
    __syncthreads();
    for (int o = 128; o; o >>= 1) {
        if (threadIdx.x < o) sh[threadIdx.x] += sh[threadIdx.x + o];
        __syncthreads();
    }
    if (threadIdx.x == 0) g_part[blockIdx.x] = sh[0];
}

__global__ void wsum2_kernel(float* __restrict__ out) {
    __shared__ double sh[1024];
    sh[threadIdx.x] = (double)g_part[threadIdx.x];
    __syncthreads();
    for (int o = 512; o; o >>= 1) {
        if (threadIdx.x < o) sh[threadIdx.x] += sh[threadIdx.x + o];
        __syncthreads();
    }
    if (threadIdx.x == 0) out[0] = (float)sh[0];
}

// ---------------- launch ----------------
extern "C" void kernel_launch(void* const* d_in, const int* in_sizes, int n_in,
                              void* d_out, int out_size) {
    const float* X1 = (const float*)d_in[0];
    const float* X2 = (const float*)d_in[2];
    float* out = (float*)d_out;

    init_kernel<<<16, 256>>>();
    sqnorm_kernel<<<dim3(NPTS / 8, 2), 256>>>(X1, X2);
    dist_kernel<<<dim3(64, 64, 2), dim3(16, 16)>>>(X1, X2);
    minmax_kernel<<<dim3(32, 2), 256>>>();
    hist_kernel<<<dim3(64, 2), 256>>>();
    tau_kernel<<<2, 1024>>>();
    pfill_kernel<<<dim3((NPTS * NPTS) / 256, 2), 256>>>();

    for (int r = 0; r < CROUNDS; r++) {
        cmin_kernel<<<dim3(64, 2), 256>>>();
        bmerge_kernel<<<2, 1024>>>();
    }
    for (int r = 0; r < DROUNDS; r++) {
        bmin_kernel<<<dim3(NPTS / 8, 2), 256>>>();
        bmerge_kernel<<<2, 1024>>>();
    }

    fixup_kernel<<<(2 * NEDGE + 255) / 256, 256>>>();

    unsigned *keys, *alt;
    void* tempp;
    cudaGetSymbolAddress((void**)&keys, g_keys);
    cudaGetSymbolAddress((void**)&alt, g_keysAlt);
    cudaGetSymbolAddress(&tempp, g_temp);

    cub::DoubleBuffer<unsigned> db(keys, alt);
    size_t bytes = 0;
    cub::DeviceRadixSort::SortKeys(nullptr, bytes, db, TOTKEYS, 0, 32, (cudaStream_t)0);
    cub::DeviceRadixSort::SortKeys(tempp, bytes, db, TOTKEYS, 0, 32, (cudaStream_t)0);

    const unsigned* sorted = db.Current();
    wsum1_kernel<<<1024, 256>>>(sorted);
    wsum2_kernel<<<1, 1024>>>(out);
}